// round 1
// baseline (speedup 1.0000x reference)
#include <cuda_runtime.h>
#include <cuda_bf16.h>

// Problem constants (fixed by reference setup_inputs)
#define BATCH 2
#define HH 48
#define WW 48
#define CC 512
#define NH 8
#define HD 64
#define KK 7
#define NPIX (BATCH*HH*WW)          // 4608
#define QKV_M (3*CC)                 // 1536

// Scratch (static device globals — allowed; runtime allocation is not)
__device__ float g_qkv[(size_t)NPIX * QKV_M];   // 28.3 MB: [pixel][3*512], layout (part, head, d)
__device__ float g_att[(size_t)NPIX * CC];      // 9.4 MB:  [pixel][512]

// ---------------------------------------------------------------------------
// SGEMM  C[N,M] = A[N,K] * B[M,K]^T + bias[M]
// Both A and B row-major with K contiguous (NT form). 128x128 tile, BK=8,
// 256 threads, 8x8 per-thread microtile, float4 global loads, fused bias.
// Requires N%128==0, M%128==0, K%8==0 (true for both GEMMs here).
// ---------------------------------------------------------------------------
__global__ __launch_bounds__(256) void sgemm_nt_bias(
    const float* __restrict__ A, const float* __restrict__ B,
    const float* __restrict__ bias, float* __restrict__ C,
    int N, int M, int K)
{
    __shared__ float As[8][128];
    __shared__ float Bs[8][128];

    const int tid = threadIdx.x;
    const int n0 = blockIdx.y * 128;
    const int m0 = blockIdx.x * 128;

    // loading map: 256 threads -> 128 rows x 2 float4 (8 k-values per row)
    const int lr = tid >> 1;            // 0..127
    const int lc = (tid & 1) << 2;      // 0 or 4

    // compute map
    const int tx = tid & 15;            // m micro
    const int ty = tid >> 4;            // n micro

    const float* Aptr = A + (size_t)(n0 + lr) * K + lc;
    const float* Bptr = B + (size_t)(m0 + lr) * K + lc;

    float acc[8][8];
    #pragma unroll
    for (int i = 0; i < 8; i++)
        #pragma unroll
        for (int j = 0; j < 8; j++) acc[i][j] = 0.f;

    for (int k0 = 0; k0 < K; k0 += 8) {
        float4 a4 = *(const float4*)(Aptr + k0);
        float4 b4 = *(const float4*)(Bptr + k0);
        As[lc + 0][lr] = a4.x; As[lc + 1][lr] = a4.y;
        As[lc + 2][lr] = a4.z; As[lc + 3][lr] = a4.w;
        Bs[lc + 0][lr] = b4.x; Bs[lc + 1][lr] = b4.y;
        Bs[lc + 2][lr] = b4.z; Bs[lc + 3][lr] = b4.w;
        __syncthreads();

        #pragma unroll
        for (int kk = 0; kk < 8; kk++) {
            float4 a0 = *(const float4*)&As[kk][ty * 8];
            float4 a1 = *(const float4*)&As[kk][ty * 8 + 4];
            float4 b0 = *(const float4*)&Bs[kk][tx * 8];
            float4 b1 = *(const float4*)&Bs[kk][tx * 8 + 4];
            float ar[8] = {a0.x, a0.y, a0.z, a0.w, a1.x, a1.y, a1.z, a1.w};
            float br[8] = {b0.x, b0.y, b0.z, b0.w, b1.x, b1.y, b1.z, b1.w};
            #pragma unroll
            for (int i = 0; i < 8; i++)
                #pragma unroll
                for (int j = 0; j < 8; j++)
                    acc[i][j] += ar[i] * br[j];
        }
        __syncthreads();
    }

    // epilogue with bias
    float bb[8];
    #pragma unroll
    for (int j = 0; j < 8; j++) bb[j] = bias[m0 + tx * 8 + j];

    #pragma unroll
    for (int i = 0; i < 8; i++) {
        float* crow = C + (size_t)(n0 + ty * 8 + i) * M + m0 + tx * 8;
        float4 o0, o1;
        o0.x = acc[i][0] + bb[0]; o0.y = acc[i][1] + bb[1];
        o0.z = acc[i][2] + bb[2]; o0.w = acc[i][3] + bb[3];
        o1.x = acc[i][4] + bb[4]; o1.y = acc[i][5] + bb[5];
        o1.z = acc[i][6] + bb[6]; o1.w = acc[i][7] + bb[7];
        *(float4*)(crow)     = o0;
        *(float4*)(crow + 4) = o1;
    }
}

// ---------------------------------------------------------------------------
// Neighborhood attention. Block = one head x one 8x8 pixel tile, 256 threads
// (4 threads per pixel, each owning 16 of the 64 head dims).
// The union of all 64 windows in a tile spans <= 14x14 pixels; K/V for that
// window are staged in smem in [d][pix] layout, padded stride 197.
// ---------------------------------------------------------------------------
#define WIN 14
#define KSTR 197
#define SC_STR 50
#define SMEM_NATT ((2*HD*KSTR + 64*HD + 64*SC_STR) * (int)sizeof(float))  // 130048 B

__global__ __launch_bounds__(256) void natt_kernel(
    const float* __restrict__ qkv, float* __restrict__ out)
{
    extern __shared__ float smem[];
    float* ks = smem;                    // [64][197]
    float* vs = ks + HD * KSTR;          // [64][197]
    float* qs = vs + HD * KSTR;          // [64][64]
    float* sc = qs + 64 * HD;            // [64][50]

    const int tile = blockIdx.x;         // 0..35
    const int h = blockIdx.y;            // 0..7
    const int b = blockIdx.z;            // 0..1
    const int ti0 = (tile / 6) * 8;
    const int tj0 = (tile % 6) * 8;
    const int wr0 = min(max(ti0 - 3, 0), HH - WIN);  // window base row
    const int wc0 = min(max(tj0 - 3, 0), WW - WIN);  // window base col

    const int t = threadIdx.x;
    const float* base = qkv + (size_t)b * HH * WW * QKV_M;

    // stage Q tile (coalesced)
    for (int v = t; v < 64 * 16; v += 256) {
        int pix = v >> 4, dc = v & 15;
        int gi = ti0 + (pix >> 3), gj = tj0 + (pix & 7);
        float4 f = *(const float4*)(base + ((size_t)gi * WW + gj) * QKV_M + h * HD + dc * 4);
        *(float4*)(qs + pix * HD + dc * 4) = f;
    }
    // stage K,V window (transposed into [d][pix])
    for (int v = t; v < WIN * WIN * 16; v += 256) {
        int wpix = v >> 4, dc = v & 15;
        int wr = wr0 + wpix / WIN, wc = wc0 + wpix % WIN;
        const float* p = base + ((size_t)wr * WW + wc) * QKV_M + CC + h * HD + dc * 4;
        float4 kf = *(const float4*)p;
        float4 vf = *(const float4*)(p + CC);
        int d0 = dc * 4;
        ks[(d0 + 0) * KSTR + wpix] = kf.x;
        ks[(d0 + 1) * KSTR + wpix] = kf.y;
        ks[(d0 + 2) * KSTR + wpix] = kf.z;
        ks[(d0 + 3) * KSTR + wpix] = kf.w;
        vs[(d0 + 0) * KSTR + wpix] = vf.x;
        vs[(d0 + 1) * KSTR + wpix] = vf.y;
        vs[(d0 + 2) * KSTR + wpix] = vf.z;
        vs[(d0 + 3) * KSTR + wpix] = vf.w;
    }
    __syncthreads();

    const int pix = t >> 2;              // 0..63
    const int sub = t & 3;               // 0..3 (16 dims each)
    const int pi = pix >> 3, pj = pix & 7;
    const int gi = ti0 + pi, gj = tj0 + pj;
    const int ro = min(max(gi - 3, 0), HH - KK) - wr0;   // 0..7
    const int co = min(max(gj - 3, 0), WW - KK) - wc0;

    float qreg[16];
    #pragma unroll
    for (int d = 0; d < 16; d++)
        qreg[d] = qs[pix * HD + sub * 16 + d] * 0.125f;   // hd^-0.5

    float* mysc = sc + pix * SC_STR;

    // pass 1: scores + max (shuffle-reduce over the 4 sub-lanes)
    float mx = -1e30f;
    #pragma unroll
    for (int p = 0; p < KK; p++) {
        #pragma unroll
        for (int q = 0; q < KK; q++) {
            int wp = (ro + p) * WIN + (co + q);
            const float* kp = ks + (sub * 16) * KSTR + wp;
            float s = 0.f;
            #pragma unroll
            for (int d = 0; d < 16; d++) s += qreg[d] * kp[d * KSTR];
            s += __shfl_xor_sync(0xffffffffu, s, 1);
            s += __shfl_xor_sync(0xffffffffu, s, 2);
            mx = fmaxf(mx, s);
            int n = p * KK + q;
            if ((n & 3) == sub) mysc[n] = s;
        }
    }
    __syncwarp();

    // pass 2: exp distributed across the 4 sub-lanes (MUFU is scarce)
    float lsum = 0.f;
    for (int n = sub; n < KK * KK; n += 4) {
        float w = __expf(mysc[n] - mx);
        mysc[n] = w;
        lsum += w;
    }
    lsum += __shfl_xor_sync(0xffffffffu, lsum, 1);
    lsum += __shfl_xor_sync(0xffffffffu, lsum, 2);
    __syncwarp();

    // pass 3: weighted V accumulation
    float acc[16];
    #pragma unroll
    for (int d = 0; d < 16; d++) acc[d] = 0.f;
    #pragma unroll
    for (int p = 0; p < KK; p++) {
        #pragma unroll
        for (int q = 0; q < KK; q++) {
            int n = p * KK + q;
            float w = mysc[n];
            int wp = (ro + p) * WIN + (co + q);
            const float* vp = vs + (sub * 16) * KSTR + wp;
            #pragma unroll
            for (int d = 0; d < 16; d++) acc[d] += w * vp[d * KSTR];
        }
    }

    float inv = 1.f / lsum;
    float* op = out + ((size_t)b * HH * WW + (size_t)gi * WW + gj) * CC + h * HD + sub * 16;
    #pragma unroll
    for (int d = 0; d < 16; d += 4) {
        float4 f;
        f.x = acc[d + 0] * inv; f.y = acc[d + 1] * inv;
        f.z = acc[d + 2] * inv; f.w = acc[d + 3] * inv;
        *(float4*)(op + d) = f;
    }
}

// ---------------------------------------------------------------------------
extern "C" void kernel_launch(void* const* d_in, const int* in_sizes, int n_in,
                              void* d_out, int out_size)
{
    (void)in_sizes; (void)n_in; (void)out_size;
    const float* x      = (const float*)d_in[0];
    const float* qkv_w  = (const float*)d_in[1];
    const float* qkv_b  = (const float*)d_in[2];
    const float* proj_w = (const float*)d_in[3];
    const float* proj_b = (const float*)d_in[4];
    float* out = (float*)d_out;

    float *qkv_s = nullptr, *att_s = nullptr;
    cudaGetSymbolAddress((void**)&qkv_s, g_qkv);
    cudaGetSymbolAddress((void**)&att_s, g_att);

    // 1) QKV projection: [4608,512] x [512,1536]^T + bias
    {
        dim3 grid(QKV_M / 128, NPIX / 128);   // (12, 36)
        sgemm_nt_bias<<<grid, 256>>>(x, qkv_w, qkv_b, qkv_s, NPIX, QKV_M, CC);
    }

    // 2) neighborhood attention
    {
        cudaFuncSetAttribute(natt_kernel, cudaFuncAttributeMaxDynamicSharedMemorySize, SMEM_NATT);
        dim3 grid(36, NH, BATCH);
        natt_kernel<<<grid, 256, SMEM_NATT>>>(qkv_s, att_s);
    }

    // 3) output projection: [4608,512] x [512,512]^T + bias
    {
        dim3 grid(CC / 128, NPIX / 128);      // (4, 36)
        sgemm_nt_bias<<<grid, 256>>>(att_s, proj_w, proj_b, out, NPIX, CC, CC);
    }
}

// round 3
// speedup vs baseline: 2.2401x; 2.2401x over previous
#include <cuda_runtime.h>
#include <cstdint>

// Problem constants (fixed by reference setup_inputs)
#define BATCH 2
#define HH 48
#define WW 48
#define CC 512
#define NH 8
#define HD 64
#define KK 7
#define NPIX (BATCH*HH*WW)          // 4608
#define QKV_M (3*CC)                 // 1536

// Scratch (static device globals)
__device__ float g_qkv[(size_t)NPIX * QKV_M];   // 28.3 MB
__device__ float g_att[(size_t)NPIX * CC];      // 9.4 MB

// ---------------------------------------------------------------------------
// helpers
// ---------------------------------------------------------------------------
__device__ __forceinline__ uint32_t smem_u32(const void* p) {
    uint32_t a;
    asm("{ .reg .u64 t; cvta.to.shared.u64 t, %1; cvt.u32.u64 %0, t; }" : "=r"(a) : "l"(p));
    return a;
}
__device__ __forceinline__ uint32_t f2tf32(float x) {
    uint32_t r; asm("cvt.rna.tf32.f32 %0, %1;" : "=r"(r) : "f"(x)); return r;
}
#define CP16(dst, src)  asm volatile("cp.async.cg.shared.global [%0], [%1], 16;" :: "r"(dst), "l"(src) : "memory")
#define CP_COMMIT()     asm volatile("cp.async.commit_group;" ::: "memory")
#define CP_WAIT(n)      asm volatile("cp.async.wait_group %0;" :: "n"(n) : "memory")

#define MMA_TF32(c, a, b) \
    asm volatile("mma.sync.aligned.m16n8k8.row.col.f32.tf32.tf32.f32 " \
        "{%0,%1,%2,%3}, {%4,%5,%6,%7}, {%8,%9}, {%0,%1,%2,%3};" \
        : "+f"((c)[0]), "+f"((c)[1]), "+f"((c)[2]), "+f"((c)[3]) \
        : "r"((a)[0]), "r"((a)[1]), "r"((a)[2]), "r"((a)[3]), "r"((b)[0]), "r"((b)[1]))

// ---------------------------------------------------------------------------
// tf32 warp-MMA GEMM:  C[M][Ncols] = A[M,K] * B[Ncols,K]^T + bias[Ncols]
// CTA tile 128x128, BK=32, 8 warps (2x4), warp tile 64x32 (4x4 of m16n8k8).
// SMEM rows padded to 36 floats -> every fragment LDS is bank-conflict-free
// (addr mod 32 = 4*group + tig, a 32-lane permutation).
// Requires M%128==0, Ncols%128==0, K%32==0.
// ---------------------------------------------------------------------------
#define BM 128
#define BN 128
#define ASTR 36
#define STG_BYTES (128*ASTR*4)       // 18432 per buffer
#define SM_GEMM (4*STG_BYTES)        // 73728: A[2], B[2]

__global__ __launch_bounds__(256, 2) void gemm_mma(
    const float* __restrict__ A, const float* __restrict__ B,
    const float* __restrict__ bias, float* __restrict__ C,
    int K, int Ncols)
{
    extern __shared__ float sm[];
    const uint32_t sb = smem_u32(sm);

    const int t = threadIdx.x;
    const int lane = t & 31, wid = t >> 5;
    const int g = lane >> 2, tg = lane & 3;
    const int wm = wid >> 2, wn = wid & 3;
    const int m0 = blockIdx.y * BM, n0 = blockIdx.x * BN;

    const int ldr = t >> 3;          // 0..31 base row (+32*i)
    const int ldc = t & 7;           // float4 index within 32-float row

    float acc[4][4][4];
    #pragma unroll
    for (int i = 0; i < 4; i++)
        #pragma unroll
        for (int j = 0; j < 4; j++)
            #pragma unroll
            for (int r = 0; r < 4; r++) acc[i][j][r] = 0.f;

    const int nch = K >> 5;

    // ---- async copy of one K-chunk into buffer `buf`
    auto issue = [&](int ch, int buf) {
        const float* Ac = A + (size_t)m0 * K + ch * 32;
        const float* Bc = B + (size_t)n0 * K + ch * 32;
        uint32_t dA = sb + buf * STG_BYTES;
        uint32_t dB = sb + 2 * STG_BYTES + buf * STG_BYTES;
        #pragma unroll
        for (int i = 0; i < 4; i++) {
            int row = ldr + i * 32;
            CP16(dA + row * (ASTR * 4) + ldc * 16, Ac + (size_t)row * K + ldc * 4);
        }
        #pragma unroll
        for (int i = 0; i < 4; i++) {
            int row = ldr + i * 32;
            CP16(dB + row * (ASTR * 4) + ldc * 16, Bc + (size_t)row * K + ldc * 4);
        }
        CP_COMMIT();
    };

    issue(0, 0);

    for (int ch = 0; ch < nch; ch++) {
        const int buf = ch & 1;
        if (ch + 1 < nch) {
            issue(ch + 1, buf ^ 1);
            CP_WAIT(1);
        } else {
            CP_WAIT(0);
        }
        __syncthreads();

        const float* Ab = sm + buf * (128 * ASTR);
        const float* Bb = sm + 2 * (128 * ASTR) + buf * (128 * ASTR);

        #pragma unroll
        for (int kk = 0; kk < 4; kk++) {
            uint32_t af[4][4], bf[4][2];
            #pragma unroll
            for (int mt = 0; mt < 4; mt++) {
                const float* p = Ab + (wm * 64 + mt * 16 + g) * ASTR + kk * 8 + tg;
                af[mt][0] = f2tf32(p[0]);
                af[mt][1] = f2tf32(p[8 * ASTR]);
                af[mt][2] = f2tf32(p[4]);
                af[mt][3] = f2tf32(p[8 * ASTR + 4]);
            }
            #pragma unroll
            for (int nt = 0; nt < 4; nt++) {
                const float* p = Bb + (wn * 32 + nt * 8 + g) * ASTR + kk * 8 + tg;
                bf[nt][0] = f2tf32(p[0]);
                bf[nt][1] = f2tf32(p[4]);
            }
            #pragma unroll
            for (int mt = 0; mt < 4; mt++)
                #pragma unroll
                for (int nt = 0; nt < 4; nt++)
                    MMA_TF32(acc[mt][nt], af[mt], bf[nt]);
        }
        __syncthreads();
    }

    // epilogue: c0,c1 -> (row, col..col+1); c2,c3 -> (row+8, ...)
    float bb[4][2];
    #pragma unroll
    for (int nt = 0; nt < 4; nt++) {
        int c = n0 + wn * 32 + nt * 8 + 2 * tg;
        bb[nt][0] = __ldg(bias + c);
        bb[nt][1] = __ldg(bias + c + 1);
    }
    #pragma unroll
    for (int mt = 0; mt < 4; mt++) {
        int r = m0 + wm * 64 + mt * 16 + g;
        #pragma unroll
        for (int nt = 0; nt < 4; nt++) {
            int c = n0 + wn * 32 + nt * 8 + 2 * tg;
            float2 v0 = { acc[mt][nt][0] + bb[nt][0], acc[mt][nt][1] + bb[nt][1] };
            float2 v1 = { acc[mt][nt][2] + bb[nt][0], acc[mt][nt][3] + bb[nt][1] };
            *(float2*)(C + (size_t)r * Ncols + c) = v0;
            *(float2*)(C + (size_t)(r + 8) * Ncols + c) = v1;
        }
    }
}

// ---------------------------------------------------------------------------
// Neighborhood attention (unchanged, correct since round 1).
// ---------------------------------------------------------------------------
#define WIN 14
#define KSTR 197
#define SC_STR 50
#define SMEM_NATT ((2*HD*KSTR + 64*HD + 64*SC_STR) * (int)sizeof(float))  // 130048 B

__global__ __launch_bounds__(256) void natt_kernel(
    const float* __restrict__ qkv, float* __restrict__ out)
{
    extern __shared__ float smemf[];
    float* ks = smemf;
    float* vs = ks + HD * KSTR;
    float* qs = vs + HD * KSTR;
    float* sc = qs + 64 * HD;

    const int tile = blockIdx.x;
    const int h = blockIdx.y;
    const int b = blockIdx.z;
    const int ti0 = (tile / 6) * 8;
    const int tj0 = (tile % 6) * 8;
    const int wr0 = min(max(ti0 - 3, 0), HH - WIN);
    const int wc0 = min(max(tj0 - 3, 0), WW - WIN);

    const int t = threadIdx.x;
    const float* base = qkv + (size_t)b * HH * WW * QKV_M;

    for (int v = t; v < 64 * 16; v += 256) {
        int pix = v >> 4, dc = v & 15;
        int gi = ti0 + (pix >> 3), gj = tj0 + (pix & 7);
        float4 f = *(const float4*)(base + ((size_t)gi * WW + gj) * QKV_M + h * HD + dc * 4);
        *(float4*)(qs + pix * HD + dc * 4) = f;
    }
    for (int v = t; v < WIN * WIN * 16; v += 256) {
        int wpix = v >> 4, dc = v & 15;
        int wr = wr0 + wpix / WIN, wc = wc0 + wpix % WIN;
        const float* p = base + ((size_t)wr * WW + wc) * QKV_M + CC + h * HD + dc * 4;
        float4 kf = *(const float4*)p;
        float4 vf = *(const float4*)(p + CC);
        int d0 = dc * 4;
        ks[(d0 + 0) * KSTR + wpix] = kf.x;
        ks[(d0 + 1) * KSTR + wpix] = kf.y;
        ks[(d0 + 2) * KSTR + wpix] = kf.z;
        ks[(d0 + 3) * KSTR + wpix] = kf.w;
        vs[(d0 + 0) * KSTR + wpix] = vf.x;
        vs[(d0 + 1) * KSTR + wpix] = vf.y;
        vs[(d0 + 2) * KSTR + wpix] = vf.z;
        vs[(d0 + 3) * KSTR + wpix] = vf.w;
    }
    __syncthreads();

    const int pix = t >> 2;
    const int sub = t & 3;
    const int pi = pix >> 3, pj = pix & 7;
    const int gi = ti0 + pi, gj = tj0 + pj;
    const int ro = min(max(gi - 3, 0), HH - KK) - wr0;
    const int co = min(max(gj - 3, 0), WW - KK) - wc0;

    float qreg[16];
    #pragma unroll
    for (int d = 0; d < 16; d++)
        qreg[d] = qs[pix * HD + sub * 16 + d] * 0.125f;

    float* mysc = sc + pix * SC_STR;

    float mx = -1e30f;
    #pragma unroll
    for (int p = 0; p < KK; p++) {
        #pragma unroll
        for (int q = 0; q < KK; q++) {
            int wp = (ro + p) * WIN + (co + q);
            const float* kp = ks + (sub * 16) * KSTR + wp;
            float s = 0.f;
            #pragma unroll
            for (int d = 0; d < 16; d++) s += qreg[d] * kp[d * KSTR];
            s += __shfl_xor_sync(0xffffffffu, s, 1);
            s += __shfl_xor_sync(0xffffffffu, s, 2);
            mx = fmaxf(mx, s);
            int n = p * KK + q;
            if ((n & 3) == sub) mysc[n] = s;
        }
    }
    __syncwarp();

    float lsum = 0.f;
    for (int n = sub; n < KK * KK; n += 4) {
        float w = __expf(mysc[n] - mx);
        mysc[n] = w;
        lsum += w;
    }
    lsum += __shfl_xor_sync(0xffffffffu, lsum, 1);
    lsum += __shfl_xor_sync(0xffffffffu, lsum, 2);
    __syncwarp();

    float acc[16];
    #pragma unroll
    for (int d = 0; d < 16; d++) acc[d] = 0.f;
    #pragma unroll
    for (int p = 0; p < KK; p++) {
        #pragma unroll
        for (int q = 0; q < KK; q++) {
            int n = p * KK + q;
            float w = mysc[n];
            int wp = (ro + p) * WIN + (co + q);
            const float* vp = vs + (sub * 16) * KSTR + wp;
            #pragma unroll
            for (int d = 0; d < 16; d++) acc[d] += w * vp[d * KSTR];
        }
    }

    float inv = 1.f / lsum;
    float* op = out + ((size_t)b * HH * WW + (size_t)gi * WW + gj) * CC + h * HD + sub * 16;
    #pragma unroll
    for (int d = 0; d < 16; d += 4) {
        float4 f;
        f.x = acc[d + 0] * inv; f.y = acc[d + 1] * inv;
        f.z = acc[d + 2] * inv; f.w = acc[d + 3] * inv;
        *(float4*)(op + d) = f;
    }
}

// ---------------------------------------------------------------------------
extern "C" void kernel_launch(void* const* d_in, const int* in_sizes, int n_in,
                              void* d_out, int out_size)
{
    (void)in_sizes; (void)n_in; (void)out_size;
    const float* x      = (const float*)d_in[0];
    const float* qkv_w  = (const float*)d_in[1];
    const float* qkv_b  = (const float*)d_in[2];
    const float* proj_w = (const float*)d_in[3];
    const float* proj_b = (const float*)d_in[4];
    float* out = (float*)d_out;

    float *qkv_s = nullptr, *att_s = nullptr;
    cudaGetSymbolAddress((void**)&qkv_s, g_qkv);
    cudaGetSymbolAddress((void**)&att_s, g_att);

    cudaFuncSetAttribute(gemm_mma, cudaFuncAttributeMaxDynamicSharedMemorySize, SM_GEMM);
    cudaFuncSetAttribute(natt_kernel, cudaFuncAttributeMaxDynamicSharedMemorySize, SMEM_NATT);

    // 1) QKV projection: [4608,512] x [512,1536]^T + bias  (tf32 HMMA)
    {
        dim3 grid(QKV_M / BN, NPIX / BM);     // (12, 36)
        gemm_mma<<<grid, 256, SM_GEMM>>>(x, qkv_w, qkv_b, qkv_s, CC, QKV_M);
    }
    // 2) neighborhood attention
    {
        dim3 grid(36, NH, BATCH);
        natt_kernel<<<grid, 256, SMEM_NATT>>>(qkv_s, att_s);
    }
    // 3) output projection: [4608,512] x [512,512]^T + bias
    {
        dim3 grid(CC / BN, NPIX / BM);        // (4, 36)
        gemm_mma<<<grid, 256, SM_GEMM>>>(att_s, proj_w, proj_b, out, CC, CC);
    }
}

// round 4
// speedup vs baseline: 2.6861x; 1.1991x over previous
#include <cuda_runtime.h>
#include <cstdint>

// Problem constants (fixed by reference setup_inputs)
#define BATCH 2
#define HH 48
#define WW 48
#define CC 512
#define NH 8
#define HD 64
#define KK 7
#define NPIX (BATCH*HH*WW)          // 4608
#define QKV_M (3*CC)                 // 1536

// Scratch (static device globals)
__device__ float g_qkv[(size_t)NPIX * QKV_M];   // 28.3 MB
__device__ float g_att[(size_t)NPIX * CC];      // 9.4 MB

// ---------------------------------------------------------------------------
// helpers
// ---------------------------------------------------------------------------
__device__ __forceinline__ uint32_t smem_u32(const void* p) {
    uint32_t a;
    asm("{ .reg .u64 t; cvta.to.shared.u64 t, %1; cvt.u32.u64 %0, t; }" : "=r"(a) : "l"(p));
    return a;
}
__device__ __forceinline__ uint32_t f2tf32(float x) {
    uint32_t r; asm("cvt.rna.tf32.f32 %0, %1;" : "=r"(r) : "f"(x)); return r;
}
__device__ __forceinline__ float f2tf32f(float x) {
    return __uint_as_float(f2tf32(x));
}
#define CP16(dst, src)  asm volatile("cp.async.cg.shared.global [%0], [%1], 16;" :: "r"(dst), "l"(src) : "memory")
#define CP_COMMIT()     asm volatile("cp.async.commit_group;" ::: "memory")
#define CP_WAIT(n)      asm volatile("cp.async.wait_group %0;" :: "n"(n) : "memory")

#define MMA_TF32(c, a, b) \
    asm volatile("mma.sync.aligned.m16n8k8.row.col.f32.tf32.tf32.f32 " \
        "{%0,%1,%2,%3}, {%4,%5,%6,%7}, {%8,%9}, {%0,%1,%2,%3};" \
        : "+f"((c)[0]), "+f"((c)[1]), "+f"((c)[2]), "+f"((c)[3]) \
        : "r"((a)[0]), "r"((a)[1]), "r"((a)[2]), "r"((a)[3]), "r"((b)[0]), "r"((b)[1]))

// ---------------------------------------------------------------------------
// tf32 warp-MMA GEMM (unchanged from round 3, known-good):
// C[M][Ncols] = A[M,K] * B[Ncols,K]^T + bias[Ncols]
// ---------------------------------------------------------------------------
#define BM 128
#define BN 128
#define ASTR 36
#define STG_BYTES (128*ASTR*4)
#define SM_GEMM (4*STG_BYTES)

__global__ __launch_bounds__(256, 2) void gemm_mma(
    const float* __restrict__ A, const float* __restrict__ B,
    const float* __restrict__ bias, float* __restrict__ C,
    int K, int Ncols)
{
    extern __shared__ float sm[];
    const uint32_t sb = smem_u32(sm);

    const int t = threadIdx.x;
    const int lane = t & 31, wid = t >> 5;
    const int g = lane >> 2, tg = lane & 3;
    const int wm = wid >> 2, wn = wid & 3;
    const int m0 = blockIdx.y * BM, n0 = blockIdx.x * BN;

    const int ldr = t >> 3;
    const int ldc = t & 7;

    float acc[4][4][4];
    #pragma unroll
    for (int i = 0; i < 4; i++)
        #pragma unroll
        for (int j = 0; j < 4; j++)
            #pragma unroll
            for (int r = 0; r < 4; r++) acc[i][j][r] = 0.f;

    const int nch = K >> 5;

    auto issue = [&](int ch, int buf) {
        const float* Ac = A + (size_t)m0 * K + ch * 32;
        const float* Bc = B + (size_t)n0 * K + ch * 32;
        uint32_t dA = sb + buf * STG_BYTES;
        uint32_t dB = sb + 2 * STG_BYTES + buf * STG_BYTES;
        #pragma unroll
        for (int i = 0; i < 4; i++) {
            int row = ldr + i * 32;
            CP16(dA + row * (ASTR * 4) + ldc * 16, Ac + (size_t)row * K + ldc * 4);
        }
        #pragma unroll
        for (int i = 0; i < 4; i++) {
            int row = ldr + i * 32;
            CP16(dB + row * (ASTR * 4) + ldc * 16, Bc + (size_t)row * K + ldc * 4);
        }
        CP_COMMIT();
    };

    issue(0, 0);

    for (int ch = 0; ch < nch; ch++) {
        const int buf = ch & 1;
        if (ch + 1 < nch) { issue(ch + 1, buf ^ 1); CP_WAIT(1); }
        else              { CP_WAIT(0); }
        __syncthreads();

        const float* Ab = sm + buf * (128 * ASTR);
        const float* Bb = sm + 2 * (128 * ASTR) + buf * (128 * ASTR);

        #pragma unroll
        for (int kk = 0; kk < 4; kk++) {
            uint32_t af[4][4], bf[4][2];
            #pragma unroll
            for (int mt = 0; mt < 4; mt++) {
                const float* p = Ab + (wm * 64 + mt * 16 + g) * ASTR + kk * 8 + tg;
                af[mt][0] = f2tf32(p[0]);
                af[mt][1] = f2tf32(p[8 * ASTR]);
                af[mt][2] = f2tf32(p[4]);
                af[mt][3] = f2tf32(p[8 * ASTR + 4]);
            }
            #pragma unroll
            for (int nt = 0; nt < 4; nt++) {
                const float* p = Bb + (wn * 32 + nt * 8 + g) * ASTR + kk * 8 + tg;
                bf[nt][0] = f2tf32(p[0]);
                bf[nt][1] = f2tf32(p[4]);
            }
            #pragma unroll
            for (int mt = 0; mt < 4; mt++)
                #pragma unroll
                for (int nt = 0; nt < 4; nt++)
                    MMA_TF32(acc[mt][nt], af[mt], bf[nt]);
        }
        __syncthreads();
    }

    float bb[4][2];
    #pragma unroll
    for (int nt = 0; nt < 4; nt++) {
        int c = n0 + wn * 32 + nt * 8 + 2 * tg;
        bb[nt][0] = __ldg(bias + c);
        bb[nt][1] = __ldg(bias + c + 1);
    }
    #pragma unroll
    for (int mt = 0; mt < 4; mt++) {
        int r = m0 + wm * 64 + mt * 16 + g;
        #pragma unroll
        for (int nt = 0; nt < 4; nt++) {
            int c = n0 + wn * 32 + nt * 8 + 2 * tg;
            float2 v0 = { acc[mt][nt][0] + bb[nt][0], acc[mt][nt][1] + bb[nt][1] };
            float2 v1 = { acc[mt][nt][2] + bb[nt][0], acc[mt][nt][3] + bb[nt][1] };
            *(float2*)(C + (size_t)r * Ncols + c) = v0;
            *(float2*)(C + (size_t)(r + 8) * Ncols + c) = v1;
        }
    }
}

// ---------------------------------------------------------------------------
// Tensor-core neighborhood attention.
// Block = (head, 8x8 pixel tile). 256 threads = 8 warps.
//   S[64,208] = Q[64,64] * Kw[208,64]^T   (mma, window padded 196->208)
//   masked softmax (unnormalized weights; invalid taps -> 0)
//   O[64,64]  = W[64,208] * Vt^T          (mma; Vt is [d][winpix])
// Strides 68 / 212 make every fragment LDS a 32-bank permutation.
// ---------------------------------------------------------------------------
#define WIN 14
#define NWIN 196
#define NPAD 208
#define QSTR 68
#define WSTR 212

#define OFF_Q  0
#define OFF_K  (OFF_Q + 64*QSTR)            // 4352
#define OFF_V  (OFF_K + NPAD*QSTR)          // 18496
#define OFF_W  (OFF_V + 64*WSTR)            // 32064
#define OFF_I  (OFF_W + 64*WSTR)            // 45632
#define SM_NATT ((OFF_I + 64) * 4)          // 182784 B

__global__ __launch_bounds__(256) void natt_mma(
    const float* __restrict__ qkv, float* __restrict__ out)
{
    extern __shared__ float sm[];
    float* Qs = sm + OFF_Q;
    float* Kw = sm + OFF_K;
    float* Vt = sm + OFF_V;
    float* Ws = sm + OFF_W;
    float* invs = sm + OFF_I;

    const int tile = blockIdx.x;
    const int h = blockIdx.y;
    const int b = blockIdx.z;
    const int ti0 = (tile / 6) * 8;
    const int tj0 = (tile % 6) * 8;
    const int wr0 = min(max(ti0 - 3, 0), HH - WIN);
    const int wc0 = min(max(tj0 - 3, 0), WW - WIN);

    const int t = threadIdx.x;
    const int lane = t & 31, wid = t >> 5;
    const int g = lane >> 2, tg = lane & 3;
    const float* base = qkv + (size_t)b * HH * WW * QKV_M;

    // ---- stage Q (scaled + tf32-rounded), [64][68]
    #pragma unroll
    for (int v = t; v < 64 * 16; v += 256) {
        int pix = v >> 4, dc = v & 15;
        int gi = ti0 + (pix >> 3), gj = tj0 + (pix & 7);
        float4 f = *(const float4*)(base + ((size_t)gi * WW + gj) * QKV_M + h * HD + dc * 4);
        uint4 u = { f2tf32(f.x * 0.125f), f2tf32(f.y * 0.125f),
                    f2tf32(f.z * 0.125f), f2tf32(f.w * 0.125f) };
        *(uint4*)(Qs + pix * QSTR + dc * 4) = u;
    }
    // ---- stage K [winpix][68] and V transposed [d][212]
    if (t < NWIN) {
        int wr = wr0 + t / WIN, wc = wc0 + t % WIN;
        const float* p = base + ((size_t)wr * WW + wc) * QKV_M + CC + h * HD;
        #pragma unroll
        for (int dc = 0; dc < 16; dc++) {
            float4 kf = *(const float4*)(p + dc * 4);
            float4 vf = *(const float4*)(p + CC + dc * 4);
            uint4 u = { f2tf32(kf.x), f2tf32(kf.y), f2tf32(kf.z), f2tf32(kf.w) };
            *(uint4*)(Kw + t * QSTR + dc * 4) = u;
            int d0 = dc * 4;
            Vt[(d0 + 0) * WSTR + t] = f2tf32f(vf.x);
            Vt[(d0 + 1) * WSTR + t] = f2tf32f(vf.y);
            Vt[(d0 + 2) * WSTR + t] = f2tf32f(vf.z);
            Vt[(d0 + 3) * WSTR + t] = f2tf32f(vf.w);
        }
    }
    // zero Vt pad columns 196..211 (so 0-weights never meet garbage)
    #pragma unroll
    for (int v = t; v < 64 * 16; v += 256) {
        Vt[(v >> 4) * WSTR + NWIN + (v & 15)] = 0.f;
    }
    __syncthreads();

    // ---- QK^T: warp (wm 0..3, wn 0..1); m-tile = 16 rows, n-range = 104 cols
    {
        const int wm = wid >> 1, wn = wid & 1;
        float acc[13][4];
        #pragma unroll
        for (int nt = 0; nt < 13; nt++)
            #pragma unroll
            for (int r = 0; r < 4; r++) acc[nt][r] = 0.f;

        const float* q0 = Qs + (wm * 16 + g) * QSTR + tg;
        const float* q1 = q0 + 8 * QSTR;
        const float* kb = Kw + (wn * 104 + g) * QSTR + tg;

        #pragma unroll
        for (int k = 0; k < 8; k++) {
            uint32_t af[4];
            af[0] = __float_as_uint(q0[k * 8]);
            af[1] = __float_as_uint(q1[k * 8]);
            af[2] = __float_as_uint(q0[k * 8 + 4]);
            af[3] = __float_as_uint(q1[k * 8 + 4]);
            #pragma unroll
            for (int nt = 0; nt < 13; nt++) {
                uint32_t bf[2];
                const float* p = kb + nt * 8 * QSTR + k * 8;
                bf[0] = __float_as_uint(p[0]);
                bf[1] = __float_as_uint(p[4]);
                MMA_TF32(acc[nt], af, bf);
            }
        }
        // write scores to Ws
        #pragma unroll
        for (int nt = 0; nt < 13; nt++) {
            int r = wm * 16 + g;
            int n = wn * 104 + nt * 8 + 2 * tg;
            *(float2*)(Ws + r * WSTR + n) = make_float2(acc[nt][0], acc[nt][1]);
            *(float2*)(Ws + (r + 8) * WSTR + n) = make_float2(acc[nt][2], acc[nt][3]);
        }
    }
    __syncthreads();

    // ---- masked softmax (unnormalized); 4 threads per pixel
    {
        const int pix = t >> 2, sub = t & 3;
        const int gi = ti0 + (pix >> 3), gj = tj0 + (pix & 7);
        const int ro = min(max(gi - 3, 0), HH - KK) - wr0;
        const int co = min(max(gj - 3, 0), WW - KK) - wc0;
        float* wrow = Ws + pix * WSTR;

        float mx = -1e30f;
        #pragma unroll 4
        for (int i = 0; i < 52; i++) {
            int n = sub + 4 * i;
            if (n < NWIN) {
                int wr = n / WIN, wc = n - wr * WIN;
                if ((unsigned)(wr - ro) < 7u && (unsigned)(wc - co) < 7u)
                    mx = fmaxf(mx, wrow[n]);
            }
        }
        mx = fmaxf(mx, __shfl_xor_sync(0xffffffffu, mx, 1));
        mx = fmaxf(mx, __shfl_xor_sync(0xffffffffu, mx, 2));

        float lsum = 0.f;
        #pragma unroll 4
        for (int i = 0; i < 52; i++) {
            int n = sub + 4 * i;
            float w = 0.f;
            if (n < NWIN) {
                int wr = n / WIN, wc = n - wr * WIN;
                if ((unsigned)(wr - ro) < 7u && (unsigned)(wc - co) < 7u) {
                    w = __expf(wrow[n] - mx);
                }
            }
            wrow[n] = f2tf32f(w);
            lsum += w;
        }
        lsum += __shfl_xor_sync(0xffffffffu, lsum, 1);
        lsum += __shfl_xor_sync(0xffffffffu, lsum, 2);
        if (sub == 0) invs[pix] = 1.f / lsum;
    }
    __syncthreads();

    // ---- O = W * V : warp (wm 0..3, wn 0..1); n-range = 32 cols
    {
        const int wm = wid >> 1, wn = wid & 1;
        float acc[4][4];
        #pragma unroll
        for (int nt = 0; nt < 4; nt++)
            #pragma unroll
            for (int r = 0; r < 4; r++) acc[nt][r] = 0.f;

        const float* w0 = Ws + (wm * 16 + g) * WSTR + tg;
        const float* w1 = w0 + 8 * WSTR;
        const float* vb = Vt + (wn * 32 + g) * WSTR + tg;

        #pragma unroll 2
        for (int kb = 0; kb < 26; kb++) {
            uint32_t af[4];
            af[0] = __float_as_uint(w0[kb * 8]);
            af[1] = __float_as_uint(w1[kb * 8]);
            af[2] = __float_as_uint(w0[kb * 8 + 4]);
            af[3] = __float_as_uint(w1[kb * 8 + 4]);
            #pragma unroll
            for (int nt = 0; nt < 4; nt++) {
                uint32_t bf[2];
                const float* p = vb + nt * 8 * WSTR + kb * 8;
                bf[0] = __float_as_uint(p[0]);
                bf[1] = __float_as_uint(p[4]);
                MMA_TF32(acc[nt], af, bf);
            }
        }

        const int r = wm * 16 + g;
        const float inv0 = invs[r], inv1 = invs[r + 8];
        const int gi0 = ti0 + (r >> 3), gj0 = tj0 + (r & 7);
        const int r1 = r + 8;
        const int gi1 = ti0 + (r1 >> 3), gj1 = tj0 + (r1 & 7);
        float* o0 = out + ((size_t)b * HH * WW + (size_t)gi0 * WW + gj0) * CC + h * HD;
        float* o1 = out + ((size_t)b * HH * WW + (size_t)gi1 * WW + gj1) * CC + h * HD;
        #pragma unroll
        for (int nt = 0; nt < 4; nt++) {
            int c = wn * 32 + nt * 8 + 2 * tg;
            *(float2*)(o0 + c) = make_float2(acc[nt][0] * inv0, acc[nt][1] * inv0);
            *(float2*)(o1 + c) = make_float2(acc[nt][2] * inv1, acc[nt][3] * inv1);
        }
    }
}

// ---------------------------------------------------------------------------
extern "C" void kernel_launch(void* const* d_in, const int* in_sizes, int n_in,
                              void* d_out, int out_size)
{
    (void)in_sizes; (void)n_in; (void)out_size;
    const float* x      = (const float*)d_in[0];
    const float* qkv_w  = (const float*)d_in[1];
    const float* qkv_b  = (const float*)d_in[2];
    const float* proj_w = (const float*)d_in[3];
    const float* proj_b = (const float*)d_in[4];
    float* out = (float*)d_out;

    float *qkv_s = nullptr, *att_s = nullptr;
    cudaGetSymbolAddress((void**)&qkv_s, g_qkv);
    cudaGetSymbolAddress((void**)&att_s, g_att);

    cudaFuncSetAttribute(gemm_mma, cudaFuncAttributeMaxDynamicSharedMemorySize, SM_GEMM);
    cudaFuncSetAttribute(natt_mma, cudaFuncAttributeMaxDynamicSharedMemorySize, SM_NATT);

    // 1) QKV projection: [4608,512] x [512,1536]^T + bias  (tf32 HMMA)
    {
        dim3 grid(QKV_M / BN, NPIX / BM);     // (12, 36)
        gemm_mma<<<grid, 256, SM_GEMM>>>(x, qkv_w, qkv_b, qkv_s, CC, QKV_M);
    }
    // 2) neighborhood attention (tf32 HMMA)
    {
        dim3 grid(36, NH, BATCH);
        natt_mma<<<grid, 256, SM_NATT>>>(qkv_s, att_s);
    }
    // 3) output projection: [4608,512] x [512,512]^T + bias
    {
        dim3 grid(CC / BN, NPIX / BM);        // (4, 36)
        gemm_mma<<<grid, 256, SM_GEMM>>>(att_s, proj_w, proj_b, out, CC, CC);
    }
}